// round 15
// baseline (speedup 1.0000x reference)
#include <cuda_runtime.h>
#include <cuda_bf16.h>
#include <cstdint>

#define EMB 1024
#define NH 16
#define HD 64
#define SEQ 8192
#define GL 128
#define BLK 512
#define NB 16
#define LTOT 8320
#define GSPLIT 10
#define GTPS 13

// ================= scratch =================
__device__ __nv_bfloat16 g_Xhi[(size_t)LTOT * EMB];
__device__ __nv_bfloat16 g_Xlo[(size_t)LTOT * EMB];
__device__ __nv_bfloat16 g_Whi[(size_t)4 * EMB * EMB];  // transposed [N,K]
__device__ __nv_bfloat16 g_Wlo[(size_t)4 * EMB * EMB];
__device__ __nv_bfloat16 g_Qhi[(size_t)LTOT * EMB];
__device__ __nv_bfloat16 g_Qlo[(size_t)LTOT * EMB];
__device__ __nv_bfloat16 g_Khi[(size_t)LTOT * EMB];
__device__ __nv_bfloat16 g_Klo[(size_t)LTOT * EMB];
__device__ __nv_bfloat16 g_Vhi[(size_t)LTOT * EMB];
__device__ __nv_bfloat16 g_Vlo[(size_t)LTOT * EMB];
__device__ float g_part[(size_t)NH * GSPLIT * GL * (HD + 2)];

// ================= PTX helpers =================
__device__ __forceinline__ uint32_t smem_u32(const void* p) {
    uint32_t a;
    asm("{ .reg .u64 t; cvta.to.shared.u64 t, %1; cvt.u32.u64 %0, t; }" : "=r"(a) : "l"(p));
    return a;
}
__device__ __forceinline__ void cp16(uint32_t s, const void* g) {
    asm volatile("cp.async.cg.shared.global [%0], [%1], 16;" :: "r"(s), "l"(g));
}
#define CP_COMMIT() asm volatile("cp.async.commit_group;" ::: "memory")
#define CP_WAIT(n)  asm volatile("cp.async.wait_group %0;" :: "n"(n) : "memory")

#define LDSM_X4(r, addr)                                                          \
    asm volatile("ldmatrix.sync.aligned.m8n8.x4.shared.b16 {%0,%1,%2,%3},[%4];"   \
        : "=r"((r)[0]), "=r"((r)[1]), "=r"((r)[2]), "=r"((r)[3]) : "r"(addr))
#define LDSM_T4(r, addr)                                                          \
    asm volatile("ldmatrix.sync.aligned.m8n8.x4.trans.shared.b16 {%0,%1,%2,%3},[%4];" \
        : "=r"((r)[0]), "=r"((r)[1]), "=r"((r)[2]), "=r"((r)[3]) : "r"(addr))

#define MMA_BF16(c, a, b0v, b1v)                                                   \
    asm volatile("mma.sync.aligned.m16n8k16.row.col.f32.bf16.bf16.f32 "            \
        "{%0,%1,%2,%3},{%4,%5,%6,%7},{%8,%9},{%0,%1,%2,%3};"                       \
        : "+f"((c)[0]), "+f"((c)[1]), "+f"((c)[2]), "+f"((c)[3])                   \
        : "r"((a)[0]), "r"((a)[1]), "r"((a)[2]), "r"((a)[3]),                      \
          "r"(b0v), "r"(b1v))

__device__ __forceinline__ void split2(float x, float y, uint32_t& hi, uint32_t& lo) {
    __nv_bfloat16 hx = __float2bfloat16_rn(x), hy = __float2bfloat16_rn(y);
    __nv_bfloat16 lx = __float2bfloat16_rn(x - __bfloat162float(hx));
    __nv_bfloat16 ly = __float2bfloat16_rn(y - __bfloat162float(hy));
    __nv_bfloat162 h2 = __halves2bfloat162(hx, hy);
    __nv_bfloat162 l2 = __halves2bfloat162(lx, ly);
    hi = *(uint32_t*)&h2;
    lo = *(uint32_t*)&l2;
}
__device__ __forceinline__ uint32_t pack_bf2(float x, float y) {
    __nv_bfloat162 h2 = __halves2bfloat162(__float2bfloat16_rn(x), __float2bfloat16_rn(y));
    return *(uint32_t*)&h2;
}

// ================= conversion kernels =================
__global__ void cvt_x(const float4* __restrict__ glob, const float4* __restrict__ tok) {
    size_t i = (size_t)blockIdx.x * blockDim.x + threadIdx.x;
    size_t gl4 = (size_t)GL * EMB / 4, tot4 = (size_t)LTOT * EMB / 4;
    if (i >= tot4) return;
    float4 v = (i < gl4) ? glob[i] : tok[i - gl4];
    __nv_bfloat16 h[4], lo[4];
    float f[4] = {v.x, v.y, v.z, v.w};
#pragma unroll
    for (int j = 0; j < 4; j++) {
        h[j] = __float2bfloat16_rn(f[j]);
        lo[j] = __float2bfloat16_rn(f[j] - __bfloat162float(h[j]));
    }
    *(ushort4*)&g_Xhi[i * 4] = *(ushort4*)h;
    *(ushort4*)&g_Xlo[i * 4] = *(ushort4*)lo;
}

__global__ void cvt_w(const float* __restrict__ W0, const float* __restrict__ W1,
                      const float* __restrict__ W2, const float* __restrict__ W3) {
    __shared__ float s[32][33];
    int w = blockIdx.z;
    const float* W = (w == 0) ? W0 : (w == 1) ? W1 : (w == 2) ? W2 : W3;
    __nv_bfloat16* hi = g_Whi + ((size_t)w << 20);
    __nv_bfloat16* lo = g_Wlo + ((size_t)w << 20);
    int k0 = blockIdx.x * 32, n0 = blockIdx.y * 32;
    int tx = threadIdx.x, ty = threadIdx.y;
#pragma unroll
    for (int i = 0; i < 4; i++)
        s[ty + i * 8][tx] = W[(size_t)(k0 + ty + i * 8) * EMB + n0 + tx];
    __syncthreads();
#pragma unroll
    for (int i = 0; i < 4; i++) {
        float v = s[tx][ty + i * 8];
        __nv_bfloat16 h = __float2bfloat16_rn(v);
        size_t off = (size_t)(n0 + ty + i * 8) * EMB + k0 + tx;
        hi[off] = h;
        lo[off] = __float2bfloat16_rn(v - __bfloat162float(h));
    }
}

// ================= bf16 split-GEMM core (R12 proven: BK=32, 4-stage) =========
__device__ __forceinline__ void gload(uint32_t sbase,
    const __nv_bfloat16* __restrict__ Asrc, const __nv_bfloat16* __restrict__ Bsrc,
    int m0, int n0, int ksub, const int* ldr, const int* ldso, const int* ldch) {
#pragma unroll
    for (int i = 0; i < 2; i++) {
        cp16(sbase + ldso[i], Asrc + (size_t)(m0 + ldr[i]) * EMB + ksub + ldch[i]);
        cp16(sbase + 8192 + ldso[i], Bsrc + (size_t)(n0 + ldr[i]) * EMB + ksub + ldch[i]);
    }
}

__device__ __forceinline__ void gemm_core(
    const __nv_bfloat16* __restrict__ Ahi, const __nv_bfloat16* __restrict__ Alo,
    const __nv_bfloat16* __restrict__ Bhi, const __nv_bfloat16* __restrict__ Blo,
    float* __restrict__ C, float scale,
    __nv_bfloat16* __restrict__ Chi, __nv_bfloat16* __restrict__ Clo,
    int m0, int n0, char* gsm) {

    int t = threadIdx.x, lane = t & 31, wid = t >> 5;
    int wm = wid >> 1, wn = wid & 1;
    uint32_t sb = smem_u32(gsm);

    int khalfA = (lane >> 4) & 1;
    int rA = (lane & 7) + ((lane >> 3) & 1) * 8;
    int baseA[2], swA[2];
#pragma unroll
    for (int mt = 0; mt < 2; mt++) {
        int row = wm * 32 + mt * 16 + rA;
        baseA[mt] = row * 64;
        swA[mt] = (row >> 1) & 3;
    }
    int khalfB = (lane >> 3) & 1;
    int baseB[4], swB[4];
#pragma unroll
    for (int j = 0; j < 4; j++) {
        int row = wn * 64 + (2 * j + ((lane >> 4) & 1)) * 8 + (lane & 7);
        baseB[j] = row * 64;
        swB[j] = (row >> 1) & 3;
    }

    int ldr[2], ldso[2], ldch[2];
#pragma unroll
    for (int i = 0; i < 2; i++) {
        int idx = t + i * 256;
        int r = idx >> 2, ch = idx & 3;
        ldr[i] = r;
        ldso[i] = r * 64 + ((ch ^ ((r >> 1) & 3)) << 4);
        ldch[i] = ch * 8;
    }

    float c[2][8][4];
#pragma unroll
    for (int mt = 0; mt < 2; mt++)
#pragma unroll
        for (int nt = 0; nt < 8; nt++)
#pragma unroll
            for (int k = 0; k < 4; k++) c[mt][nt][k] = 0.f;

#pragma unroll
    for (int s = 0; s < 3; s++) {
        gload(sb + s * 16384, Ahi, Bhi, m0, n0, s * 32, ldr, ldso, ldch);
        CP_COMMIT();
    }

    for (int kt = 0; kt < 96; kt++) {
        CP_WAIT(2);
        __syncthreads();
        int kn = kt + 3;
        if (kn < 96) {
            int p = kn >> 5, ksub = (kn & 31) * 32;
            gload(sb + (kn & 3) * 16384,
                  (p == 1) ? Alo : Ahi, (p == 2) ? Blo : Bhi,
                  m0, n0, ksub, ldr, ldso, ldch);
        }
        CP_COMMIT();

        uint32_t bb = sb + (kt & 3) * 16384;
#pragma unroll
        for (int ks = 0; ks < 2; ks++) {
            uint32_t af[2][4], bf[8][2];
#pragma unroll
            for (int mt = 0; mt < 2; mt++) {
                uint32_t addr = bb + baseA[mt] + (((ks * 2 + khalfA) ^ swA[mt]) << 4);
                LDSM_X4(af[mt], addr);
            }
#pragma unroll
            for (int j = 0; j < 4; j++) {
                uint32_t r[4];
                uint32_t addr = bb + 8192 + baseB[j] + (((ks * 2 + khalfB) ^ swB[j]) << 4);
                LDSM_X4(r, addr);
                bf[2 * j][0] = r[0]; bf[2 * j][1] = r[1];
                bf[2 * j + 1][0] = r[2]; bf[2 * j + 1][1] = r[3];
            }
#pragma unroll
            for (int mt = 0; mt < 2; mt++)
#pragma unroll
                for (int nt = 0; nt < 8; nt++)
                    MMA_BF16(c[mt][nt], af[mt], bf[nt][0], bf[nt][1]);
        }
    }

    int g = lane >> 2, tig = lane & 3;
#pragma unroll
    for (int mt = 0; mt < 2; mt++) {
#pragma unroll
        for (int nt = 0; nt < 8; nt++) {
            int row = m0 + wm * 32 + mt * 16 + g;
            int col = n0 + wn * 64 + nt * 8 + tig * 2;
            if (Chi) {
                uint32_t h0, l0, h1, l1;
                split2(c[mt][nt][0] * scale, c[mt][nt][1] * scale, h0, l0);
                split2(c[mt][nt][2] * scale, c[mt][nt][3] * scale, h1, l1);
                *(uint32_t*)(Chi + (size_t)row * EMB + col) = h0;
                *(uint32_t*)(Clo + (size_t)row * EMB + col) = l0;
                *(uint32_t*)(Chi + (size_t)(row + 8) * EMB + col) = h1;
                *(uint32_t*)(Clo + (size_t)(row + 8) * EMB + col) = l1;
            } else {
                float2 v0 = {c[mt][nt][0] * scale, c[mt][nt][1] * scale};
                float2 v1 = {c[mt][nt][2] * scale, c[mt][nt][3] * scale};
                *(float2*)(C + (size_t)row * EMB + col) = v0;
                *(float2*)(C + (size_t)(row + 8) * EMB + col) = v1;
            }
        }
    }
}

// merged Q/K/V projection: grid (24, 65)
__global__ __launch_bounds__(256, 2) void gemm_qkv() {
    extern __shared__ __align__(128) char gsm[];
    int w = blockIdx.x >> 3;
    int n0 = (blockIdx.x & 7) * 128;
    int m0 = blockIdx.y * 128;
    const size_t WSZ = (size_t)EMB * EMB;
    __nv_bfloat16* Chi = (w == 0) ? g_Qhi : (w == 1) ? g_Khi : g_Vhi;
    __nv_bfloat16* Clo = (w == 0) ? g_Qlo : (w == 1) ? g_Klo : g_Vlo;
    float scale = (w == 0) ? 0.125f : 1.f;
    gemm_core(g_Xhi, g_Xlo, g_Whi + w * WSZ, g_Wlo + w * WSZ,
              nullptr, scale, Chi, Clo, m0, n0, gsm);
}

// output projection: grid (8, 65), fp32 out
__global__ __launch_bounds__(256, 2) void gemm_wo(float* __restrict__ C) {
    extern __shared__ __align__(128) char gsm[];
    const size_t WSZ = (size_t)EMB * EMB;
    gemm_core(g_Xhi, g_Xlo, g_Whi + 3 * WSZ, g_Wlo + 3 * WSZ,
              C, 1.f, nullptr, nullptr, blockIdx.y * 128, blockIdx.x * 128, gsm);
}

// ================= FA2-style attention (256 thr, 128 q rows/CTA, 3-stage) ====
// CTAs [0, 160): global-partial; [160, 1184): local.
#define STG 33024
#define N_G_CTAS 160
__global__ __launch_bounds__(256, 1) void fmha(const float* __restrict__ mask) {
    extern __shared__ __align__(128) char smem[];
    int t = threadIdx.x, lane = t & 31, wid = t >> 5;   // wid 0..7
    int g = lane >> 2, tq = lane & 3;
    int bid = blockIdx.x;
    int mode, h, n = 0, ks = 0, qrow0, NT;
    if (bid < N_G_CTAS) {
        mode = 1;
        ks = bid % GSPLIT;
        h = bid / GSPLIT;
        qrow0 = wid * 16;                                 // 128 global q rows
        NT = GTPS;
    } else {
        mode = 0;
        int r = bid - N_G_CTAS;
        int qt = r & 3;
        n = (r >> 2) & 15;
        h = r >> 6;
        qrow0 = GL + n * BLK + qt * 128 + wid * 16;
        NT = 10;
    }
    uint32_t sb = smem_u32(smem);

    uint32_t qh[4][4], ql[4][4];
    {
        size_t r0 = (size_t)(qrow0 + g) * EMB + h * HD;
        size_t r1 = (size_t)(qrow0 + g + 8) * EMB + h * HD;
#pragma unroll
        for (int kf = 0; kf < 4; kf++) {
            int c0 = kf * 16 + 2 * tq, c1 = kf * 16 + 8 + 2 * tq;
            qh[kf][0] = *(const uint32_t*)(g_Qhi + r0 + c0);
            qh[kf][1] = *(const uint32_t*)(g_Qhi + r1 + c0);
            qh[kf][2] = *(const uint32_t*)(g_Qhi + r0 + c1);
            qh[kf][3] = *(const uint32_t*)(g_Qhi + r1 + c1);
            ql[kf][0] = *(const uint32_t*)(g_Qlo + r0 + c0);
            ql[kf][1] = *(const uint32_t*)(g_Qlo + r1 + c0);
            ql[kf][2] = *(const uint32_t*)(g_Qlo + r0 + c1);
            ql[kf][3] = *(const uint32_t*)(g_Qlo + r1 + c1);
        }
    }

    float m0 = -1e30f, m1 = -1e30f, l0 = 0.f, l1 = 0.f;
    float o[8][4];
#pragma unroll
    for (int i = 0; i < 8; i++)
#pragma unroll
        for (int j = 0; j < 4; j++) o[i][j] = 0.f;

#define ISSUE(tile, stage)                                                         \
    do {                                                                           \
        int krow0_ = (mode == 0)                                                   \
            ? ((tile) < 2 ? (tile) * 64 : GL + n * BLK + ((tile) - 2) * 64)        \
            : (ks * GTPS + (tile)) * 64;                                           \
        uint32_t base_ = sb + (stage) * STG;                                       \
        _Pragma("unroll")                                                          \
        for (int rep = 0; rep < 2; rep++) {                                        \
            int idx = rep * 256 + t;                                               \
            int row = idx >> 3, ch = idx & 7;                                      \
            uint32_t so = row * 128 + ((ch ^ (row & 7)) << 4);                     \
            size_t go = (size_t)(krow0_ + row) * EMB + h * HD + ch * 8;            \
            cp16(base_ + so,          g_Khi + go);                                 \
            cp16(base_ + 8192 + so,   g_Klo + go);                                 \
            cp16(base_ + 16384 + so,  g_Vhi + go);                                 \
            cp16(base_ + 24576 + so,  g_Vlo + go);                                 \
        }                                                                          \
        if (t < 64) {                                                              \
            float mv;                                                              \
            if (mode == 0) mv = ((tile) < 2) ? 0.f : mask[n * BLK + ((tile) - 2) * 64 + t]; \
            else { int x_ = krow0_ + t; mv = (x_ < GL) ? 0.f : mask[x_ - GL]; }    \
            *(float*)(smem + (stage) * STG + 32768 + t * 4) = mv;                  \
        }                                                                          \
    } while (0)

    ISSUE(0, 0); CP_COMMIT();
    ISSUE(1, 1); CP_COMMIT();

    for (int tile = 0; tile < NT; tile++) {
        int stage = tile % 3;
        CP_WAIT(1);
        __syncthreads();
        if (tile + 2 < NT) ISSUE(tile + 2, (tile + 2) % 3);
        CP_COMMIT();

        uint32_t Kh = sb + stage * STG, Kl = Kh + 8192;
        uint32_t Vh = Kh + 16384, Vl = Kh + 24576;
        const float* Ms = (const float*)(smem + stage * STG + 32768);

        float sc[8][4];
#pragma unroll
        for (int i = 0; i < 8; i++)
#pragma unroll
            for (int j = 0; j < 4; j++) sc[i][j] = 0.f;

        int kNtile = 2 * ((lane >> 4) & 1);
        int kKey7 = lane & 7;
        int kHalf = (lane >> 3) & 1;
#pragma unroll
        for (int kf = 0; kf < 4; kf++) {
            uint32_t kb[8][2];
#pragma unroll
            for (int j = 0; j < 4; j++) {
                uint32_t r[4];
                int key = (2 * j + (kNtile >> 1)) * 8 + kKey7;
                int chunk = kf * 2 + kHalf;
                uint32_t addr = Kh + key * 128 + ((chunk ^ (key & 7)) << 4);
                LDSM_X4(r, addr);
                kb[2 * j][0] = r[0]; kb[2 * j][1] = r[1];
                kb[2 * j + 1][0] = r[2]; kb[2 * j + 1][1] = r[3];
            }
#pragma unroll
            for (int nf = 0; nf < 8; nf++) MMA_BF16(sc[nf], qh[kf], kb[nf][0], kb[nf][1]);
#pragma unroll
            for (int nf = 0; nf < 8; nf++) MMA_BF16(sc[nf], ql[kf], kb[nf][0], kb[nf][1]);
#pragma unroll
            for (int j = 0; j < 4; j++) {
                uint32_t r[4];
                int key = (2 * j + (kNtile >> 1)) * 8 + kKey7;
                int chunk = kf * 2 + kHalf;
                uint32_t addr = Kl + key * 128 + ((chunk ^ (key & 7)) << 4);
                LDSM_X4(r, addr);
                kb[2 * j][0] = r[0]; kb[2 * j][1] = r[1];
                kb[2 * j + 1][0] = r[2]; kb[2 * j + 1][1] = r[3];
            }
#pragma unroll
            for (int nf = 0; nf < 8; nf++) MMA_BF16(sc[nf], qh[kf], kb[nf][0], kb[nf][1]);
        }

        float rmax0 = -1e30f, rmax1 = -1e30f;
#pragma unroll
        for (int nf = 0; nf < 8; nf++) {
            float2 mv = *(const float2*)(Ms + nf * 8 + 2 * tq);
            sc[nf][0] += mv.x; sc[nf][1] += mv.y;
            sc[nf][2] += mv.x; sc[nf][3] += mv.y;
            rmax0 = fmaxf(rmax0, fmaxf(sc[nf][0], sc[nf][1]));
            rmax1 = fmaxf(rmax1, fmaxf(sc[nf][2], sc[nf][3]));
        }
        rmax0 = fmaxf(rmax0, __shfl_xor_sync(0xffffffffu, rmax0, 1));
        rmax0 = fmaxf(rmax0, __shfl_xor_sync(0xffffffffu, rmax0, 2));
        rmax1 = fmaxf(rmax1, __shfl_xor_sync(0xffffffffu, rmax1, 1));
        rmax1 = fmaxf(rmax1, __shfl_xor_sync(0xffffffffu, rmax1, 2));
        float mn0 = fmaxf(m0, rmax0), mn1 = fmaxf(m1, rmax1);
        float corr0 = __expf(m0 - mn0), corr1 = __expf(m1 - mn1);
        m0 = mn0; m1 = mn1;
#pragma unroll
        for (int nf = 0; nf < 8; nf++) {
            o[nf][0] *= corr0; o[nf][1] *= corr0;
            o[nf][2] *= corr1; o[nf][3] *= corr1;
        }
        float rs0 = 0.f, rs1 = 0.f;
#pragma unroll
        for (int nf = 0; nf < 8; nf++) {
            sc[nf][0] = __expf(sc[nf][0] - m0);
            sc[nf][1] = __expf(sc[nf][1] - m0);
            sc[nf][2] = __expf(sc[nf][2] - m1);
            sc[nf][3] = __expf(sc[nf][3] - m1);
            rs0 += sc[nf][0] + sc[nf][1];
            rs1 += sc[nf][2] + sc[nf][3];
        }
        rs0 += __shfl_xor_sync(0xffffffffu, rs0, 1);
        rs0 += __shfl_xor_sync(0xffffffffu, rs0, 2);
        rs1 += __shfl_xor_sync(0xffffffffu, rs1, 1);
        rs1 += __shfl_xor_sync(0xffffffffu, rs1, 2);
        l0 = l0 * corr0 + rs0;
        l1 = l1 * corr1 + rs1;

        uint32_t ph[4][4], pl[4][4];
#pragma unroll
        for (int kk = 0; kk < 4; kk++) {
            float* s0 = sc[2 * kk];
            float* s1 = sc[2 * kk + 1];
            ph[kk][0] = pack_bf2(s0[0], s0[1]);
            ph[kk][1] = pack_bf2(s0[2], s0[3]);
            ph[kk][2] = pack_bf2(s1[0], s1[1]);
            ph[kk][3] = pack_bf2(s1[2], s1[3]);
            __nv_bfloat162 b;
            b = *(__nv_bfloat162*)&ph[kk][0];
            pl[kk][0] = pack_bf2(s0[0] - __bfloat162float(b.x), s0[1] - __bfloat162float(b.y));
            b = *(__nv_bfloat162*)&ph[kk][1];
            pl[kk][1] = pack_bf2(s0[2] - __bfloat162float(b.x), s0[3] - __bfloat162float(b.y));
            b = *(__nv_bfloat162*)&ph[kk][2];
            pl[kk][2] = pack_bf2(s1[0] - __bfloat162float(b.x), s1[1] - __bfloat162float(b.y));
            b = *(__nv_bfloat162*)&ph[kk][3];
            pl[kk][3] = pack_bf2(s1[2] - __bfloat162float(b.x), s1[3] - __bfloat162float(b.y));
        }

        int grp = lane >> 3;
#pragma unroll
        for (int kk = 0; kk < 4; kk++) {
#pragma unroll
            for (int j = 0; j < 4; j++) {
                int key = kk * 16 + (grp & 1) * 8 + (lane & 7);
                int dchunk = j * 2 + (grp >> 1);
                uint32_t soff = key * 128 + ((dchunk ^ (key & 7)) << 4);
                uint32_t r[4];
                LDSM_T4(r, Vh + soff);
                MMA_BF16(o[2 * j], ph[kk], r[0], r[1]);
                MMA_BF16(o[2 * j + 1], ph[kk], r[2], r[3]);
                MMA_BF16(o[2 * j], pl[kk], r[0], r[1]);
                MMA_BF16(o[2 * j + 1], pl[kk], r[2], r[3]);
                LDSM_T4(r, Vl + soff);
                MMA_BF16(o[2 * j], ph[kk], r[0], r[1]);
                MMA_BF16(o[2 * j + 1], ph[kk], r[2], r[3]);
            }
        }
    }
#undef ISSUE

    if (mode == 0) {
        float inv0 = 1.f / l0, inv1 = 1.f / l1;
        int row0 = qrow0 - GL + g;
        int row1 = row0 + 8;
#pragma unroll
        for (int nf = 0; nf < 8; nf++) {
            int col = h * HD + nf * 8 + 2 * tq;
            uint32_t h0, lo0, h1, lo1;
            split2(o[nf][0] * inv0, o[nf][1] * inv0, h0, lo0);
            split2(o[nf][2] * inv1, o[nf][3] * inv1, h1, lo1);
            *(uint32_t*)(g_Xhi + (size_t)row0 * EMB + col) = h0;
            *(uint32_t*)(g_Xlo + (size_t)row0 * EMB + col) = lo0;
            *(uint32_t*)(g_Xhi + (size_t)row1 * EMB + col) = h1;
            *(uint32_t*)(g_Xlo + (size_t)row1 * EMB + col) = lo1;
        }
    } else {
        int qi0 = qrow0 + g;
        float* pp0 = g_part + (((size_t)h * GSPLIT + ks) * GL + qi0) * (HD + 2);
        float* pp1 = g_part + (((size_t)h * GSPLIT + ks) * GL + qi0 + 8) * (HD + 2);
        if (tq == 0) {
            pp0[0] = m0; pp0[1] = l0;
            pp1[0] = m1; pp1[1] = l1;
        }
#pragma unroll
        for (int nf = 0; nf < 8; nf++) {
            int col = nf * 8 + 2 * tq;
            pp0[2 + col] = o[nf][0]; pp0[2 + col + 1] = o[nf][1];
            pp1[2 + col] = o[nf][2]; pp1[2 + col + 1] = o[nf][3];
        }
    }
}

// ================= combine global-attn partials =================
__global__ __launch_bounds__(128) void gattn_combine() {
    int h = blockIdx.x;
    int qi = threadIdx.x;
    float M = -1e30f;
    for (int ks = 0; ks < GSPLIT; ks++) {
        const float* pp = g_part + (((size_t)h * GSPLIT + ks) * GL + qi) * (HD + 2);
        M = fmaxf(M, pp[0]);
    }
    float L = 0.f;
    float out[HD];
#pragma unroll
    for (int d = 0; d < HD; d++) out[d] = 0.f;
    for (int ks = 0; ks < GSPLIT; ks++) {
        const float* pp = g_part + (((size_t)h * GSPLIT + ks) * GL + qi) * (HD + 2);
        float w = __expf(pp[0] - M);
        L += pp[1] * w;
#pragma unroll
        for (int d = 0; d < HD; d++) out[d] += pp[2 + d] * w;
    }
    float inv = 1.f / L;
    size_t rbase = (size_t)(SEQ + qi) * EMB + h * HD;
#pragma unroll
    for (int d = 0; d < HD; d += 2) {
        uint32_t hw, lw;
        split2(out[d] * inv, out[d + 1] * inv, hw, lw);
        *(uint32_t*)(g_Xhi + rbase + d) = hw;
        *(uint32_t*)(g_Xlo + rbase + d) = lw;
    }
}

// ================= host =================
extern "C" void kernel_launch(void* const* d_in, const int* in_sizes, int n_in,
                              void* d_out, int out_size) {
    const float* tok = (const float*)d_in[0];
    const float* glob = (const float*)d_in[1];
    const float* mask = (const float*)d_in[2];
    const float* Wq = (const float*)d_in[3];
    const float* Wk = (const float*)d_in[4];
    const float* Wv = (const float*)d_in[5];
    const float* Wo = (const float*)d_in[6];
    float* out = (float*)d_out;

    static bool attr_done = false;
    if (!attr_done) {
        cudaFuncSetAttribute(gemm_qkv, cudaFuncAttributeMaxDynamicSharedMemorySize, 65536);
        cudaFuncSetAttribute(gemm_wo, cudaFuncAttributeMaxDynamicSharedMemorySize, 65536);
        cudaFuncSetAttribute(fmha, cudaFuncAttributeMaxDynamicSharedMemorySize, 3 * STG);
        attr_done = true;
    }

    // 1. convert inputs
    {
        size_t tot4 = (size_t)LTOT * EMB / 4;
        cvt_x<<<(unsigned)((tot4 + 255) / 256), 256>>>((const float4*)glob, (const float4*)tok);
    }
    cvt_w<<<dim3(32, 32, 4), dim3(32, 8)>>>(Wq, Wk, Wv, Wo);

    // 2. merged Q/K/V projections
    gemm_qkv<<<dim3(24, LTOT / 128), 256, 65536>>>();

    // 3. attention: merged global-partial + local launch, then combine
    fmha<<<N_G_CTAS + 4 * NB * NH, 256, 3 * STG>>>(mask);
    gattn_combine<<<NH, 128>>>();

    // 4. output projection -> d_out
    gemm_wo<<<dim3(8, LTOT / 128), 256, 65536>>>(out);
}